// round 8
// baseline (speedup 1.0000x reference)
#include <cuda_runtime.h>
#include <cuda_bf16.h>

// Problem constants
#define B_   256
#define S_   2048
#define VOCAB_ 10
#define E_   32
#define H_   64
#define OUT_ 10

#define NTAB (VOCAB_ * VOCAB_)   // 100 table rows
#define CHUNK 16                  // steps per logits flush
#define NCHUNK (S_ / CHUNK)       // 128
#define HCS 68                    // hc row stride in floats (16B-aligned)

typedef unsigned long long ull;

// Scratch (no cudaMalloc allowed)
__device__ __align__(16) float g_table[NTAB * H_];     // 25.6 KB
__device__ __align__(16) unsigned char g_idx[B_ * S_]; // 512 KB

// ---- packed f32x2 helpers -------------------------------------------------
__device__ __forceinline__ void fma2(ull& acc, ull a, ull b) {
    asm("fma.rn.f32x2 %0, %1, %2, %3;" : "=l"(acc) : "l"(a), "l"(b), "l"(acc));
}
__device__ __forceinline__ ull add2(ull a, ull b) {
    ull r; asm("add.rn.f32x2 %0, %1, %2;" : "=l"(r) : "l"(a), "l"(b)); return r;
}
__device__ __forceinline__ ull pack2(float lo, float hi) {
    ull r;
    asm("mov.b64 %0, {%1, %2};" : "=l"(r)
        : "r"(__float_as_uint(lo)), "r"(__float_as_uint(hi)));
    return r;
}
__device__ __forceinline__ void unpack2(ull v, float& lo, float& hi) {
    unsigned int a, b;
    asm("mov.b64 {%0, %1}, %2;" : "=r"(a), "=r"(b) : "l"(v));
    lo = __uint_as_float(a); hi = __uint_as_float(b);
}

// HW tanh: single MUFU.TANH, ~16 cyc latency. Validated R7: rel_err 1.15e-4.
__device__ __forceinline__ float fast_tanh(float x) {
    float y;
    asm("tanh.approx.f32 %0, %1;" : "=f"(y) : "f"(x));
    return y;
}

// ---------------------------------------------------------------------------
// Prep kernel: blocks [0,25) build table, rest compact indices.
// ---------------------------------------------------------------------------
#define TAB_BLOCKS 25
__global__ void prep_kernel(const int* __restrict__ num1,
                            const int* __restrict__ num2,
                            const float* __restrict__ embed,
                            const float* __restrict__ Wx,
                            const float* __restrict__ bvec) {
    if (blockIdx.x < TAB_BLOCKS) {
        int i = blockIdx.x * 256 + threadIdx.x;
        if (i < NTAB * H_) {
            int v = i >> 6, j = i & 63;
            int v1 = v / VOCAB_, v2 = v % VOCAB_;
            float acc = bvec[j];
            #pragma unroll
            for (int e = 0; e < E_; ++e) {
                acc = fmaf(embed[v1 * E_ + e], Wx[e * H_ + j], acc);
                acc = fmaf(embed[v2 * E_ + e], Wx[(E_ + e) * H_ + j], acc);
            }
            g_table[i] = acc;
        }
    } else {
        int i = (blockIdx.x - TAB_BLOCKS) * 256 + threadIdx.x;
        if (i < B_ * S_) {
            g_idx[i] = (unsigned char)(num1[i] * VOCAB_ + num2[i]);
        }
    }
}

// ---------------------------------------------------------------------------
// RNN kernel: TWO chains per 64-thread CTA (grid 128, one wave at occ 1).
// Thread j owns h_j of BOTH chains. Per barrier period: chain A's step and
// chain B's step — fully independent, so B's FMA stream issues inside A's
// tanh/add-tree stall shadow, and one __syncthreads serves two chain-steps.
// Double 16-row ring per chain -> no barrier at the logits flush.
// ---------------------------------------------------------------------------
__global__ void __launch_bounds__(64, 1)
rnn_kernel(const float* __restrict__ Wh,
           const float* __restrict__ Wd,
           const float* __restrict__ bd,
           float* __restrict__ out) {
    __shared__ __align__(16) float T_sh[NTAB * H_];       // 25600 B
    __shared__ __align__(16) float hcA[2][CHUNK * HCS];   // 8704 B ring A
    __shared__ __align__(16) float hcB[2][CHUNK * HCS];   // 8704 B ring B
    __shared__ __align__(16) ull  Wdp[OUT_ * 32];         // 2560 B packed Wd
    __shared__ float bd_sh[OUT_];

    const int tid = threadIdx.x;        // 0..63 = output index j
    const int bA  = blockIdx.x * 2;
    const int bB  = bA + 1;

    // cooperative smem fills
    for (int i = tid; i < NTAB * H_; i += 64) T_sh[i] = g_table[i];
    for (int i = tid; i < OUT_ * 32; i += 64) {
        int o = i >> 5, k2 = i & 31;
        Wdp[i] = pack2(Wd[(2 * k2) * OUT_ + o], Wd[(2 * k2 + 1) * OUT_ + o]);
    }
    if (tid < OUT_) bd_sh[tid] = bd[tid];

    // packed Wh column j (shared by both chains)
    ull wkp[32];
    #pragma unroll
    for (int i = 0; i < 32; ++i) {
        wkp[i] = pack2(Wh[(2 * i) * H_ + tid], Wh[(2 * i + 1) * H_ + tid]);
    }

    // h_{-1} = 0: chunk 0 uses half 0; its t=0 reads half 1 row 15.
    hcA[1][(CHUNK - 1) * HCS + tid] = 0.0f;
    hcB[1][(CHUNK - 1) * HCS + tid] = 0.0f;

    const unsigned char* idxA_g = &g_idx[(size_t)bA * S_];
    const unsigned char* idxB_g = &g_idx[(size_t)bB * S_];
    int4 curA = *reinterpret_cast<const int4*>(idxA_g);
    int4 curB = *reinterpret_cast<const int4*>(idxB_g);
    __syncthreads();

    for (int c = 0; c < NCHUNK; ++c) {
        const int half = c & 1;
        float* __restrict__ ringA = hcA[half];
        float* __restrict__ ringB = hcB[half];
        const float* __restrict__ oringA = hcA[half ^ 1];
        const float* __restrict__ oringB = hcB[half ^ 1];

        int4 nxtA, nxtB;
        if (c + 1 < NCHUNK) {
            nxtA = *reinterpret_cast<const int4*>(idxA_g + (c + 1) * CHUNK);
            nxtB = *reinterpret_cast<const int4*>(idxB_g + (c + 1) * CHUNK);
        }
        const unsigned int pA[4] = {
            (unsigned int)curA.x, (unsigned int)curA.y,
            (unsigned int)curA.z, (unsigned int)curA.w };
        const unsigned int pB[4] = {
            (unsigned int)curB.x, (unsigned int)curB.y,
            (unsigned int)curB.z, (unsigned int)curB.w };

        #pragma unroll
        for (int t = 0; t < CHUNK; ++t) {
            const int sh   = (t & 3) * 8;
            const int idxA = (int)((pA[t >> 2] >> sh) & 255u);
            const int idxB = (int)((pB[t >> 2] >> sh) & 255u);

            float tvA = T_sh[idxA * H_ + tid];
            float tvB = T_sh[idxB * H_ + tid];

            const float* prA = (t == 0) ? &oringA[(CHUNK - 1) * HCS]
                                        : &ringA[(t - 1) * HCS];
            const float* prB = (t == 0) ? &oringB[(CHUNK - 1) * HCS]
                                        : &ringB[(t - 1) * HCS];
            const ulonglong2* hpA = reinterpret_cast<const ulonglong2*>(prA);
            const ulonglong2* hpB = reinterpret_cast<const ulonglong2*>(prB);

            // ---- chain A dot ----
            ull a0 = pack2(tvA, 0.0f), a1 = 0, a2 = 0, a3 = 0;
            #pragma unroll
            for (int g = 0; g < 16; g += 2) {
                ulonglong2 hv0 = hpA[g];
                ulonglong2 hv1 = hpA[g + 1];
                fma2(a0, hv0.x, wkp[2 * g + 0]);
                fma2(a1, hv0.y, wkp[2 * g + 1]);
                fma2(a2, hv1.x, wkp[2 * g + 2]);
                fma2(a3, hv1.y, wkp[2 * g + 3]);
            }
            // ---- chain B dot (independent: fills A's stall shadow) ----
            ull b0 = pack2(tvB, 0.0f), b1 = 0, b2 = 0, b3 = 0;
            #pragma unroll
            for (int g = 0; g < 16; g += 2) {
                ulonglong2 hv0 = hpB[g];
                ulonglong2 hv1 = hpB[g + 1];
                fma2(b0, hv0.x, wkp[2 * g + 0]);
                fma2(b1, hv0.y, wkp[2 * g + 1]);
                fma2(b2, hv1.x, wkp[2 * g + 2]);
                fma2(b3, hv1.y, wkp[2 * g + 3]);
            }

            // ---- tails ----
            ull sA = add2(add2(a0, a1), add2(a2, a3));
            ull sB = add2(add2(b0, b1), add2(b2, b3));
            float loA, hiA, loB, hiB;
            unpack2(sA, loA, hiA);
            unpack2(sB, loB, hiB);
            float hA = fast_tanh(loA + hiA);
            float hB = fast_tanh(loB + hiB);
            ringA[t * HCS + tid] = hA;
            ringB[t * HCS + tid] = hB;
            __syncthreads();
        }

        // ---- logits flush for both chains (no barrier needed: next chunk
        // writes the other ring halves; the 16 step barriers drain reads) ----
        const int s0 = c * CHUNK;
        #pragma unroll
        for (int r = 0; r < 3; ++r) {
            int i = tid + r * 64;
            if (i < CHUNK * OUT_) {
                int t = i & 15, o = i >> 4;
                const ulonglong2* wp =
                    reinterpret_cast<const ulonglong2*>(&Wdp[o * 32]);
                const ulonglong2* hA =
                    reinterpret_cast<const ulonglong2*>(&ringA[t * HCS]);
                const ulonglong2* hB =
                    reinterpret_cast<const ulonglong2*>(&ringB[t * HCS]);
                ull a0 = pack2(bd_sh[o], 0.0f), a1 = 0;
                ull b0 = pack2(bd_sh[o], 0.0f), b1 = 0;
                #pragma unroll
                for (int g = 0; g < 16; ++g) {
                    ulonglong2 wv = wp[g];
                    ulonglong2 ha = hA[g];
                    ulonglong2 hb = hB[g];
                    fma2(a0, ha.x, wv.x);
                    fma2(a1, ha.y, wv.y);
                    fma2(b0, hb.x, wv.x);
                    fma2(b1, hb.y, wv.y);
                }
                float lo, hi; unpack2(add2(a0, a1), lo, hi);
                out[((size_t)bA * S_ + (s0 + t)) * OUT_ + o] = lo + hi;
                unpack2(add2(b0, b1), lo, hi);
                out[((size_t)bB * S_ + (s0 + t)) * OUT_ + o] = lo + hi;
            }
        }
        curA = nxtA;
        curB = nxtB;
    }
}

// ---------------------------------------------------------------------------
// Entry point
// Inputs: num1[i32 B*S], num2[i32 B*S], embed[f32 10*32], Wx[f32 64*64],
//         Wh[f32 64*64], b[f32 64], Wd[f32 64*10], bd[f32 10]
// Output: float32 [B, S, 10]
// ---------------------------------------------------------------------------
extern "C" void kernel_launch(void* const* d_in, const int* in_sizes, int n_in,
                              void* d_out, int out_size) {
    const int*   num1  = (const int*)d_in[0];
    const int*   num2  = (const int*)d_in[1];
    const float* embed = (const float*)d_in[2];
    const float* Wx    = (const float*)d_in[3];
    const float* Wh    = (const float*)d_in[4];
    const float* bvec  = (const float*)d_in[5];
    const float* Wd    = (const float*)d_in[6];
    const float* bd    = (const float*)d_in[7];
    float* out = (float*)d_out;

    const int idx_blocks = (B_ * S_ + 255) / 256;
    prep_kernel<<<TAB_BLOCKS + idx_blocks, 256>>>(num1, num2, embed, Wx, bvec);

    rnn_kernel<<<B_ / 2, 64>>>(Wh, Wd, bd, out);
}

// round 9
// speedup vs baseline: 1.0051x; 1.0051x over previous
#include <cuda_runtime.h>
#include <cuda_bf16.h>

// Problem constants
#define B_   256
#define S_   2048
#define VOCAB_ 10
#define E_   32
#define H_   64
#define OUT_ 10

#define NTAB (VOCAB_ * VOCAB_)   // 100 table rows
#define CHUNK 16                  // steps per logits flush
#define NCHUNK (S_ / CHUNK)       // 128
#define HCS 68                    // hc row stride in floats (16B-aligned)

typedef unsigned long long ull;

// Scratch (no cudaMalloc allowed)
__device__ __align__(16) float g_table[NTAB * H_];     // 25.6 KB
__device__ __align__(16) unsigned char g_idx[B_ * S_]; // 512 KB

// ---- packed f32x2 helpers -------------------------------------------------
__device__ __forceinline__ void fma2(ull& acc, ull a, ull b) {
    asm("fma.rn.f32x2 %0, %1, %2, %3;" : "=l"(acc) : "l"(a), "l"(b), "l"(acc));
}
__device__ __forceinline__ ull add2(ull a, ull b) {
    ull r; asm("add.rn.f32x2 %0, %1, %2;" : "=l"(r) : "l"(a), "l"(b)); return r;
}
__device__ __forceinline__ ull pack2(float lo, float hi) {
    ull r;
    asm("mov.b64 %0, {%1, %2};" : "=l"(r)
        : "r"(__float_as_uint(lo)), "r"(__float_as_uint(hi)));
    return r;
}
__device__ __forceinline__ void unpack2(ull v, float& lo, float& hi) {
    unsigned int a, b;
    asm("mov.b64 {%0, %1}, %2;" : "=r"(a), "=r"(b) : "l"(v));
    lo = __uint_as_float(a); hi = __uint_as_float(b);
}

// HW tanh: single MUFU.TANH, ~16 cyc latency. Validated R7: rel_err 1.15e-4.
__device__ __forceinline__ float fast_tanh(float x) {
    float y;
    asm("tanh.approx.f32 %0, %1;" : "=f"(y) : "f"(x));
    return y;
}

// ---------------------------------------------------------------------------
// Prep kernel: blocks [0,25) build table, rest compact indices.
// ---------------------------------------------------------------------------
#define TAB_BLOCKS 25
__global__ void prep_kernel(const int* __restrict__ num1,
                            const int* __restrict__ num2,
                            const float* __restrict__ embed,
                            const float* __restrict__ Wx,
                            const float* __restrict__ bvec) {
    if (blockIdx.x < TAB_BLOCKS) {
        int i = blockIdx.x * 256 + threadIdx.x;
        if (i < NTAB * H_) {
            int v = i >> 6, j = i & 63;
            int v1 = v / VOCAB_, v2 = v % VOCAB_;
            float acc = bvec[j];
            #pragma unroll
            for (int e = 0; e < E_; ++e) {
                acc = fmaf(embed[v1 * E_ + e], Wx[e * H_ + j], acc);
                acc = fmaf(embed[v2 * E_ + e], Wx[(E_ + e) * H_ + j], acc);
            }
            g_table[i] = acc;
        }
    } else {
        int i = (blockIdx.x - TAB_BLOCKS) * 256 + threadIdx.x;
        if (i < B_ * S_) {
            g_idx[i] = (unsigned char)(num1[i] * VOCAB_ + num2[i]);
        }
    }
}

// ---------------------------------------------------------------------------
// RNN kernel: TWO chains per 64-thread CTA (grid 128, one wave at occ 1).
// Thread j owns h_j of BOTH chains. Per barrier period: chain A's step and
// chain B's step — fully independent, so B's FMA stream issues inside A's
// tanh/add-tree stall shadow, and one __syncthreads serves two chain-steps.
// Double 16-row ring per chain -> no barrier at the logits flush.
// ---------------------------------------------------------------------------
__global__ void __launch_bounds__(64, 1)
rnn_kernel(const float* __restrict__ Wh,
           const float* __restrict__ Wd,
           const float* __restrict__ bd,
           float* __restrict__ out) {
    __shared__ __align__(16) float T_sh[NTAB * H_];       // 25600 B
    __shared__ __align__(16) float hcA[2][CHUNK * HCS];   // 8704 B ring A
    __shared__ __align__(16) float hcB[2][CHUNK * HCS];   // 8704 B ring B
    __shared__ __align__(16) ull  Wdp[OUT_ * 32];         // 2560 B packed Wd
    __shared__ float bd_sh[OUT_];

    const int tid = threadIdx.x;        // 0..63 = output index j
    const int bA  = blockIdx.x * 2;
    const int bB  = bA + 1;

    // cooperative smem fills
    for (int i = tid; i < NTAB * H_; i += 64) T_sh[i] = g_table[i];
    for (int i = tid; i < OUT_ * 32; i += 64) {
        int o = i >> 5, k2 = i & 31;
        Wdp[i] = pack2(Wd[(2 * k2) * OUT_ + o], Wd[(2 * k2 + 1) * OUT_ + o]);
    }
    if (tid < OUT_) bd_sh[tid] = bd[tid];

    // packed Wh column j (shared by both chains)
    ull wkp[32];
    #pragma unroll
    for (int i = 0; i < 32; ++i) {
        wkp[i] = pack2(Wh[(2 * i) * H_ + tid], Wh[(2 * i + 1) * H_ + tid]);
    }

    // h_{-1} = 0: chunk 0 uses half 0; its t=0 reads half 1 row 15.
    hcA[1][(CHUNK - 1) * HCS + tid] = 0.0f;
    hcB[1][(CHUNK - 1) * HCS + tid] = 0.0f;

    const unsigned char* idxA_g = &g_idx[(size_t)bA * S_];
    const unsigned char* idxB_g = &g_idx[(size_t)bB * S_];
    int4 curA = *reinterpret_cast<const int4*>(idxA_g);
    int4 curB = *reinterpret_cast<const int4*>(idxB_g);
    __syncthreads();

    for (int c = 0; c < NCHUNK; ++c) {
        const int half = c & 1;
        float* __restrict__ ringA = hcA[half];
        float* __restrict__ ringB = hcB[half];
        const float* __restrict__ oringA = hcA[half ^ 1];
        const float* __restrict__ oringB = hcB[half ^ 1];

        int4 nxtA, nxtB;
        if (c + 1 < NCHUNK) {
            nxtA = *reinterpret_cast<const int4*>(idxA_g + (c + 1) * CHUNK);
            nxtB = *reinterpret_cast<const int4*>(idxB_g + (c + 1) * CHUNK);
        }
        const unsigned int pA[4] = {
            (unsigned int)curA.x, (unsigned int)curA.y,
            (unsigned int)curA.z, (unsigned int)curA.w };
        const unsigned int pB[4] = {
            (unsigned int)curB.x, (unsigned int)curB.y,
            (unsigned int)curB.z, (unsigned int)curB.w };

        #pragma unroll
        for (int t = 0; t < CHUNK; ++t) {
            const int sh   = (t & 3) * 8;
            const int idxA = (int)((pA[t >> 2] >> sh) & 255u);
            const int idxB = (int)((pB[t >> 2] >> sh) & 255u);

            float tvA = T_sh[idxA * H_ + tid];
            float tvB = T_sh[idxB * H_ + tid];

            const float* prA = (t == 0) ? &oringA[(CHUNK - 1) * HCS]
                                        : &ringA[(t - 1) * HCS];
            const float* prB = (t == 0) ? &oringB[(CHUNK - 1) * HCS]
                                        : &ringB[(t - 1) * HCS];
            const ulonglong2* hpA = reinterpret_cast<const ulonglong2*>(prA);
            const ulonglong2* hpB = reinterpret_cast<const ulonglong2*>(prB);

            // ---- chain A dot ----
            ull a0 = pack2(tvA, 0.0f), a1 = 0, a2 = 0, a3 = 0;
            #pragma unroll
            for (int g = 0; g < 16; g += 2) {
                ulonglong2 hv0 = hpA[g];
                ulonglong2 hv1 = hpA[g + 1];
                fma2(a0, hv0.x, wkp[2 * g + 0]);
                fma2(a1, hv0.y, wkp[2 * g + 1]);
                fma2(a2, hv1.x, wkp[2 * g + 2]);
                fma2(a3, hv1.y, wkp[2 * g + 3]);
            }
            // ---- chain B dot (independent: fills A's stall shadow) ----
            ull b0 = pack2(tvB, 0.0f), b1 = 0, b2 = 0, b3 = 0;
            #pragma unroll
            for (int g = 0; g < 16; g += 2) {
                ulonglong2 hv0 = hpB[g];
                ulonglong2 hv1 = hpB[g + 1];
                fma2(b0, hv0.x, wkp[2 * g + 0]);
                fma2(b1, hv0.y, wkp[2 * g + 1]);
                fma2(b2, hv1.x, wkp[2 * g + 2]);
                fma2(b3, hv1.y, wkp[2 * g + 3]);
            }

            // ---- tails ----
            ull sA = add2(add2(a0, a1), add2(a2, a3));
            ull sB = add2(add2(b0, b1), add2(b2, b3));
            float loA, hiA, loB, hiB;
            unpack2(sA, loA, hiA);
            unpack2(sB, loB, hiB);
            float hA = fast_tanh(loA + hiA);
            float hB = fast_tanh(loB + hiB);
            ringA[t * HCS + tid] = hA;
            ringB[t * HCS + tid] = hB;
            __syncthreads();
        }

        // ---- logits flush for both chains (no barrier needed: next chunk
        // writes the other ring halves; the 16 step barriers drain reads) ----
        const int s0 = c * CHUNK;
        #pragma unroll
        for (int r = 0; r < 3; ++r) {
            int i = tid + r * 64;
            if (i < CHUNK * OUT_) {
                int t = i & 15, o = i >> 4;
                const ulonglong2* wp =
                    reinterpret_cast<const ulonglong2*>(&Wdp[o * 32]);
                const ulonglong2* hA =
                    reinterpret_cast<const ulonglong2*>(&ringA[t * HCS]);
                const ulonglong2* hB =
                    reinterpret_cast<const ulonglong2*>(&ringB[t * HCS]);
                ull a0 = pack2(bd_sh[o], 0.0f), a1 = 0;
                ull b0 = pack2(bd_sh[o], 0.0f), b1 = 0;
                #pragma unroll
                for (int g = 0; g < 16; ++g) {
                    ulonglong2 wv = wp[g];
                    ulonglong2 ha = hA[g];
                    ulonglong2 hb = hB[g];
                    fma2(a0, ha.x, wv.x);
                    fma2(a1, ha.y, wv.y);
                    fma2(b0, hb.x, wv.x);
                    fma2(b1, hb.y, wv.y);
                }
                float lo, hi; unpack2(add2(a0, a1), lo, hi);
                out[((size_t)bA * S_ + (s0 + t)) * OUT_ + o] = lo + hi;
                unpack2(add2(b0, b1), lo, hi);
                out[((size_t)bB * S_ + (s0 + t)) * OUT_ + o] = lo + hi;
            }
        }
        curA = nxtA;
        curB = nxtB;
    }
}

// ---------------------------------------------------------------------------
// Entry point
// Inputs: num1[i32 B*S], num2[i32 B*S], embed[f32 10*32], Wx[f32 64*64],
//         Wh[f32 64*64], b[f32 64], Wd[f32 64*10], bd[f32 10]
// Output: float32 [B, S, 10]
// ---------------------------------------------------------------------------
extern "C" void kernel_launch(void* const* d_in, const int* in_sizes, int n_in,
                              void* d_out, int out_size) {
    const int*   num1  = (const int*)d_in[0];
    const int*   num2  = (const int*)d_in[1];
    const float* embed = (const float*)d_in[2];
    const float* Wx    = (const float*)d_in[3];
    const float* Wh    = (const float*)d_in[4];
    const float* bvec  = (const float*)d_in[5];
    const float* Wd    = (const float*)d_in[6];
    const float* bd    = (const float*)d_in[7];
    float* out = (float*)d_out;

    const int idx_blocks = (B_ * S_ + 255) / 256;
    prep_kernel<<<TAB_BLOCKS + idx_blocks, 256>>>(num1, num2, embed, Wx, bvec);

    rnn_kernel<<<B_ / 2, 64>>>(Wh, Wd, bd, out);
}

// round 10
// speedup vs baseline: 1.0829x; 1.0773x over previous
#include <cuda_runtime.h>
#include <cuda_bf16.h>

// Problem constants
#define B_   256
#define S_   2048
#define VOCAB_ 10
#define E_   32
#define H_   64
#define OUT_ 10

#define NTAB (VOCAB_ * VOCAB_)   // 100 table rows
#define CHUNK 16                  // steps per logits flush
#define NCHUNK (S_ / CHUNK)       // 128
#define HCS 68                    // hc row stride in floats (16B-aligned)

typedef unsigned long long ull;

// Scratch (no cudaMalloc allowed)
__device__ __align__(16) float g_table[NTAB * H_];     // 25.6 KB
__device__ __align__(16) unsigned char g_idx[B_ * S_]; // 512 KB

// ---- packed f32x2 helpers -------------------------------------------------
__device__ __forceinline__ void fma2(ull& acc, ull a, ull b) {
    asm("fma.rn.f32x2 %0, %1, %2, %3;" : "=l"(acc) : "l"(a), "l"(b), "l"(acc));
}
__device__ __forceinline__ ull add2(ull a, ull b) {
    ull r; asm("add.rn.f32x2 %0, %1, %2;" : "=l"(r) : "l"(a), "l"(b)); return r;
}
__device__ __forceinline__ ull pack2(float lo, float hi) {
    ull r;
    asm("mov.b64 %0, {%1, %2};" : "=l"(r)
        : "r"(__float_as_uint(lo)), "r"(__float_as_uint(hi)));
    return r;
}
__device__ __forceinline__ void unpack2(ull v, float& lo, float& hi) {
    unsigned int a, b;
    asm("mov.b64 {%0, %1}, %2;" : "=r"(a), "=r"(b) : "l"(v));
    lo = __uint_as_float(a); hi = __uint_as_float(b);
}

// HW tanh: single MUFU.TANH. Validated R7: rel_err 1.15e-4.
__device__ __forceinline__ float fast_tanh(float x) {
    float y;
    asm("tanh.approx.f32 %0, %1;" : "=f"(y) : "f"(x));
    return y;
}

// ---------------------------------------------------------------------------
// Prep kernel: blocks [0,25) build table, rest compact indices.
// ---------------------------------------------------------------------------
#define TAB_BLOCKS 25
__global__ void prep_kernel(const int* __restrict__ num1,
                            const int* __restrict__ num2,
                            const float* __restrict__ embed,
                            const float* __restrict__ Wx,
                            const float* __restrict__ bvec) {
    if (blockIdx.x < TAB_BLOCKS) {
        int i = blockIdx.x * 256 + threadIdx.x;
        if (i < NTAB * H_) {
            int v = i >> 6, j = i & 63;
            int v1 = v / VOCAB_, v2 = v % VOCAB_;
            float acc = bvec[j];
            #pragma unroll
            for (int e = 0; e < E_; ++e) {
                acc = fmaf(embed[v1 * E_ + e], Wx[e * H_ + j], acc);
                acc = fmaf(embed[v2 * E_ + e], Wx[(E_ + e) * H_ + j], acc);
            }
            g_table[i] = acc;
        }
    } else {
        int i = (blockIdx.x - TAB_BLOCKS) * 256 + threadIdx.x;
        if (i < B_ * S_) {
            g_idx[i] = (unsigned char)(num1[i] * VOCAB_ + num2[i]);
        }
    }
}

// ---------------------------------------------------------------------------
// RNN kernel: one chain per CTA (grid 256), 128 threads:
//   warps 0-1 (tid<64): recurrence, identical to the 266us R7 kernel.
//   warps 2-3: logits flush for the PREVIOUS chunk, interleaved at steps
//   4/9/14 between the shared per-step __syncthreads.
// Double 16-row ring: chunk c-1's half is stable during all of chunk c,
// and the step-15 barrier orders flush reads before chunk c+1 rewrites it.
// ---------------------------------------------------------------------------
__global__ void __launch_bounds__(128, 1)
rnn_kernel(const float* __restrict__ Wh,
           const float* __restrict__ Wd,
           const float* __restrict__ bd,
           float* __restrict__ out) {
    __shared__ __align__(16) float T_sh[NTAB * H_];     // 25600 B
    __shared__ __align__(16) float hc[2][CHUNK * HCS];  // 8704 B double ring
    __shared__ __align__(16) ull  Wdp[OUT_ * 32];       // 2560 B packed Wd
    __shared__ float bd_sh[OUT_];

    const int tid = threadIdx.x;
    const int b   = blockIdx.x;
    const bool producer = (tid < 64);
    const int ft = tid - 64;            // flush-thread index (valid if !producer)

    // cooperative smem fills (all 128 threads)
    for (int i = tid; i < NTAB * H_; i += 128) T_sh[i] = g_table[i];
    for (int i = tid; i < OUT_ * 32; i += 128) {
        int o = i >> 5, k2 = i & 31;
        Wdp[i] = pack2(Wd[(2 * k2) * OUT_ + o], Wd[(2 * k2 + 1) * OUT_ + o]);
    }
    if (tid < OUT_) bd_sh[tid] = bd[tid];

    // packed Wh column j (producers only)
    ull wkp[32];
    if (producer) {
        #pragma unroll
        for (int i = 0; i < 32; ++i) {
            wkp[i] = pack2(Wh[(2 * i) * H_ + tid], Wh[(2 * i + 1) * H_ + tid]);
        }
        // h_{-1} = 0: chunk 0 uses half 0; its t=0 reads half 1 row 15.
        hc[1][(CHUNK - 1) * HCS + tid] = 0.0f;
    }

    const unsigned char* idx_g = &g_idx[(size_t)b * S_];
    int4 curidx;
    if (producer) curidx = *reinterpret_cast<const int4*>(idx_g);
    __syncthreads();

    for (int c = 0; c < NCHUNK; ++c) {
        const int half = c & 1;
        float* __restrict__ ring = hc[half];
        const float* __restrict__ oring = hc[half ^ 1];

        int4 nextidx;
        unsigned int packs[4];
        if (producer) {
            if (c + 1 < NCHUNK) {
                nextidx =
                    *reinterpret_cast<const int4*>(idx_g + (c + 1) * CHUNK);
            }
            packs[0] = (unsigned int)curidx.x;
            packs[1] = (unsigned int)curidx.y;
            packs[2] = (unsigned int)curidx.z;
            packs[3] = (unsigned int)curidx.w;
        }

        #pragma unroll
        for (int t = 0; t < CHUNK; ++t) {
            if (producer) {
                const int idx =
                    (int)((packs[t >> 2] >> ((t & 3) * 8)) & 255u);
                float tv = T_sh[idx * H_ + tid];

                const float* prow = (t == 0) ? &oring[(CHUNK - 1) * HCS]
                                             : &ring[(t - 1) * HCS];
                const ulonglong2* hp =
                    reinterpret_cast<const ulonglong2*>(prow);

                ull a0 = pack2(tv, 0.0f);
                ull a1 = 0, a2 = 0, a3 = 0;
                #pragma unroll
                for (int g = 0; g < 16; g += 2) {
                    ulonglong2 hv0 = hp[g];
                    ulonglong2 hv1 = hp[g + 1];
                    fma2(a0, hv0.x, wkp[2 * g + 0]);
                    fma2(a1, hv0.y, wkp[2 * g + 1]);
                    fma2(a2, hv1.x, wkp[2 * g + 2]);
                    fma2(a3, hv1.y, wkp[2 * g + 3]);
                }
                ull s = add2(add2(a0, a1), add2(a2, a3));
                float lo, hi; unpack2(s, lo, hi);
                float hj = fast_tanh(lo + hi);
                ring[t * HCS + tid] = hj;
            } else if (c > 0 && (t == 4 || t == 9 || t == 14)) {
                // flush one slice of chunk c-1's logits (half^1 is stable)
                const int r = (t == 4) ? 0 : (t == 9) ? 1 : 2;
                const int i = ft + r * 64;
                if (i < CHUNK * OUT_) {
                    const int tt = i & 15, o = i >> 4;
                    const ulonglong2* hp =
                        reinterpret_cast<const ulonglong2*>(&oring[tt * HCS]);
                    const ulonglong2* wp =
                        reinterpret_cast<const ulonglong2*>(&Wdp[o * 32]);
                    ull a0 = pack2(bd_sh[o], 0.0f), a1 = 0;
                    #pragma unroll
                    for (int g = 0; g < 16; ++g) {
                        ulonglong2 hv = hp[g];
                        ulonglong2 wv = wp[g];
                        fma2(a0, hv.x, wv.x);
                        fma2(a1, hv.y, wv.y);
                    }
                    float lo, hi; unpack2(add2(a0, a1), lo, hi);
                    out[((size_t)b * S_ + ((c - 1) * CHUNK + tt)) * OUT_ + o] =
                        lo + hi;
                }
            }
            __syncthreads();
        }

        if (producer) curidx = nextidx;
    }

    // ---- epilogue: flush the last chunk (c = NCHUNK-1, half 1) ----
    {
        const float* __restrict__ ring = hc[(NCHUNK - 1) & 1];
        const int s0 = (NCHUNK - 1) * CHUNK;
        #pragma unroll
        for (int r = 0; r < 2; ++r) {
            int i = tid + r * 128;
            if (i < CHUNK * OUT_) {
                int t = i & 15, o = i >> 4;
                const ulonglong2* hp =
                    reinterpret_cast<const ulonglong2*>(&ring[t * HCS]);
                const ulonglong2* wp =
                    reinterpret_cast<const ulonglong2*>(&Wdp[o * 32]);
                ull a0 = pack2(bd_sh[o], 0.0f), a1 = 0;
                #pragma unroll
                for (int g = 0; g < 16; ++g) {
                    ulonglong2 hv = hp[g];
                    ulonglong2 wv = wp[g];
                    fma2(a0, hv.x, wv.x);
                    fma2(a1, hv.y, wv.y);
                }
                float lo, hi; unpack2(add2(a0, a1), lo, hi);
                out[((size_t)b * S_ + (s0 + t)) * OUT_ + o] = lo + hi;
            }
        }
    }
}

// ---------------------------------------------------------------------------
// Entry point
// Inputs: num1[i32 B*S], num2[i32 B*S], embed[f32 10*32], Wx[f32 64*64],
//         Wh[f32 64*64], b[f32 64], Wd[f32 64*10], bd[f32 10]
// Output: float32 [B, S, 10]
// ---------------------------------------------------------------------------
extern "C" void kernel_launch(void* const* d_in, const int* in_sizes, int n_in,
                              void* d_out, int out_size) {
    const int*   num1  = (const int*)d_in[0];
    const int*   num2  = (const int*)d_in[1];
    const float* embed = (const float*)d_in[2];
    const float* Wx    = (const float*)d_in[3];
    const float* Wh    = (const float*)d_in[4];
    const float* bvec  = (const float*)d_in[5];
    const float* Wd    = (const float*)d_in[6];
    const float* bd    = (const float*)d_in[7];
    float* out = (float*)d_out;

    const int idx_blocks = (B_ * S_ + 255) / 256;
    prep_kernel<<<TAB_BLOCKS + idx_blocks, 256>>>(num1, num2, embed, Wx, bvec);

    rnn_kernel<<<B_, 128>>>(Wh, Wd, bd, out);
}

// round 11
// speedup vs baseline: 1.1638x; 1.0747x over previous
#include <cuda_runtime.h>
#include <cuda_bf16.h>

// Problem constants
#define B_   256
#define S_   2048
#define VOCAB_ 10
#define E_   32
#define H_   64
#define OUT_ 10

#define NTAB (VOCAB_ * VOCAB_)   // 100 table rows
#define CHUNK 16                  // steps per logits flush
#define NCHUNK (S_ / CHUNK)       // 128
#define HCS 68                    // hc row stride in floats (16B-aligned)

typedef unsigned long long ull;

// Scratch (no cudaMalloc allowed)
__device__ __align__(16) float g_table[NTAB * H_];     // 25.6 KB
__device__ __align__(16) unsigned char g_idx[B_ * S_]; // 512 KB

// ---- packed f32x2 helpers -------------------------------------------------
__device__ __forceinline__ void fma2(ull& acc, ull a, ull b) {
    asm("fma.rn.f32x2 %0, %1, %2, %3;" : "=l"(acc) : "l"(a), "l"(b), "l"(acc));
}
__device__ __forceinline__ ull add2(ull a, ull b) {
    ull r; asm("add.rn.f32x2 %0, %1, %2;" : "=l"(r) : "l"(a), "l"(b)); return r;
}
__device__ __forceinline__ ull pack2(float lo, float hi) {
    ull r;
    asm("mov.b64 %0, {%1, %2};" : "=l"(r)
        : "r"(__float_as_uint(lo)), "r"(__float_as_uint(hi)));
    return r;
}
__device__ __forceinline__ void unpack2(ull v, float& lo, float& hi) {
    unsigned int a, b;
    asm("mov.b64 {%0, %1}, %2;" : "=r"(a), "=r"(b) : "l"(v));
    lo = __uint_as_float(a); hi = __uint_as_float(b);
}

// HW tanh: single MUFU.TANH. Validated R7: rel_err 1.15e-4.
__device__ __forceinline__ float fast_tanh(float x) {
    float y;
    asm("tanh.approx.f32 %0, %1;" : "=f"(y) : "f"(x));
    return y;
}

// Block-wide barrier usable from divergent top-level branches.
__device__ __forceinline__ void bar0() {
    asm volatile("bar.sync 0;" ::: "memory");
}

// ---------------------------------------------------------------------------
// Prep kernel: blocks [0,25) build table, rest compact indices.
// ---------------------------------------------------------------------------
#define TAB_BLOCKS 25
__global__ void prep_kernel(const int* __restrict__ num1,
                            const int* __restrict__ num2,
                            const float* __restrict__ embed,
                            const float* __restrict__ Wx,
                            const float* __restrict__ bvec) {
    if (blockIdx.x < TAB_BLOCKS) {
        int i = blockIdx.x * 256 + threadIdx.x;
        if (i < NTAB * H_) {
            int v = i >> 6, j = i & 63;
            int v1 = v / VOCAB_, v2 = v % VOCAB_;
            float acc = bvec[j];
            #pragma unroll
            for (int e = 0; e < E_; ++e) {
                acc = fmaf(embed[v1 * E_ + e], Wx[e * H_ + j], acc);
                acc = fmaf(embed[v2 * E_ + e], Wx[(E_ + e) * H_ + j], acc);
            }
            g_table[i] = acc;
        }
    } else {
        int i = (blockIdx.x - TAB_BLOCKS) * 256 + threadIdx.x;
        if (i < B_ * S_) {
            g_idx[i] = (unsigned char)(num1[i] * VOCAB_ + num2[i]);
        }
    }
}

// ---------------------------------------------------------------------------
// RNN kernel: one chain per CTA (grid 256), 128 threads, TOP-LEVEL split:
//   warps 0-1 (tid<64): recurrence loop, byte-identical to the 266us R7
//                       kernel but with ALL flush work removed.
//   warps 2-3: consumer loop with the same barrier schedule; flush chunk
//              c-1's logits at steps 4/9/14 of chunk c.
// One divergence for the whole kernel -> no per-step BSSY/BSYNC (R10 bug).
// Both sides execute exactly 1 + NCHUNK*CHUNK bar.sync 0.
// Double 16-row ring: chunk c-1's half is stable during chunk c; the step
// barriers order flush reads before chunk c+1 rewrites that half.
// ---------------------------------------------------------------------------
__global__ void __launch_bounds__(128, 1)
rnn_kernel(const float* __restrict__ Wh,
           const float* __restrict__ Wd,
           const float* __restrict__ bd,
           float* __restrict__ out) {
    __shared__ __align__(16) float T_sh[NTAB * H_];     // 25600 B
    __shared__ __align__(16) float hc[2][CHUNK * HCS];  // 8704 B double ring
    __shared__ __align__(16) ull  Wdp[OUT_ * 32];       // 2560 B packed Wd
    __shared__ float bd_sh[OUT_];

    const int tid = threadIdx.x;
    const int b   = blockIdx.x;

    // cooperative smem fills (all 128 threads)
    for (int i = tid; i < NTAB * H_; i += 128) T_sh[i] = g_table[i];
    for (int i = tid; i < OUT_ * 32; i += 128) {
        int o = i >> 5, k2 = i & 31;
        Wdp[i] = pack2(Wd[(2 * k2) * OUT_ + o], Wd[(2 * k2 + 1) * OUT_ + o]);
    }
    if (tid < OUT_) bd_sh[tid] = bd[tid];
    if (tid < 64) {
        // h_{-1} = 0: chunk 0 uses half 0; its t=0 reads half 1 row 15.
        hc[1][(CHUNK - 1) * HCS + tid] = 0.0f;
    }
    bar0();                                  // barrier #0

    if (tid < 64) {
        // ================= PRODUCER: the recurrence =================
        ull wkp[32];
        #pragma unroll
        for (int i = 0; i < 32; ++i) {
            wkp[i] = pack2(Wh[(2 * i) * H_ + tid], Wh[(2 * i + 1) * H_ + tid]);
        }

        const unsigned char* idx_g = &g_idx[(size_t)b * S_];
        int4 curidx = *reinterpret_cast<const int4*>(idx_g);

        for (int c = 0; c < NCHUNK; ++c) {
            const int half = c & 1;
            float* __restrict__ ring = hc[half];
            const float* __restrict__ oring = hc[half ^ 1];

            int4 nextidx;
            if (c + 1 < NCHUNK) {
                nextidx =
                    *reinterpret_cast<const int4*>(idx_g + (c + 1) * CHUNK);
            }
            const unsigned int packs[4] = {
                (unsigned int)curidx.x, (unsigned int)curidx.y,
                (unsigned int)curidx.z, (unsigned int)curidx.w };

            #pragma unroll
            for (int t = 0; t < CHUNK; ++t) {
                const int idx =
                    (int)((packs[t >> 2] >> ((t & 3) * 8)) & 255u);
                float tv = T_sh[idx * H_ + tid];

                const float* prow = (t == 0) ? &oring[(CHUNK - 1) * HCS]
                                             : &ring[(t - 1) * HCS];
                const ulonglong2* hp =
                    reinterpret_cast<const ulonglong2*>(prow);

                ull a0 = pack2(tv, 0.0f);
                ull a1 = 0, a2 = 0, a3 = 0;
                #pragma unroll
                for (int g = 0; g < 16; g += 2) {
                    ulonglong2 hv0 = hp[g];
                    ulonglong2 hv1 = hp[g + 1];
                    fma2(a0, hv0.x, wkp[2 * g + 0]);
                    fma2(a1, hv0.y, wkp[2 * g + 1]);
                    fma2(a2, hv1.x, wkp[2 * g + 2]);
                    fma2(a3, hv1.y, wkp[2 * g + 3]);
                }
                ull s = add2(add2(a0, a1), add2(a2, a3));
                float lo, hi; unpack2(s, lo, hi);
                float hj = fast_tanh(lo + hi);
                ring[t * HCS + tid] = hj;
                bar0();
            }
            curidx = nextidx;
        }
    } else {
        // ================= CONSUMER: logits flush =================
        const int ft = tid - 64;    // 0..63
        for (int c = 0; c < NCHUNK; ++c) {
            const float* __restrict__ oring = hc[(c & 1) ^ 1]; // chunk c-1
            #pragma unroll
            for (int t = 0; t < CHUNK; ++t) {
                if ((t == 4 || t == 9 || t == 14) && c > 0) {
                    const int r = (t == 4) ? 0 : (t == 9) ? 1 : 2;
                    const int i = ft + r * 64;
                    if (i < CHUNK * OUT_) {
                        const int tt = i & 15, o = i >> 4;
                        const ulonglong2* hp =
                            reinterpret_cast<const ulonglong2*>(
                                &oring[tt * HCS]);
                        const ulonglong2* wp =
                            reinterpret_cast<const ulonglong2*>(&Wdp[o * 32]);
                        ull a0 = pack2(bd_sh[o], 0.0f), a1 = 0;
                        #pragma unroll
                        for (int g = 0; g < 16; ++g) {
                            ulonglong2 hv = hp[g];
                            ulonglong2 wv = wp[g];
                            fma2(a0, hv.x, wv.x);
                            fma2(a1, hv.y, wv.y);
                        }
                        float lo, hi; unpack2(add2(a0, a1), lo, hi);
                        out[((size_t)b * S_ +
                             ((c - 1) * CHUNK + tt)) * OUT_ + o] = lo + hi;
                    }
                }
                bar0();
            }
        }
    }

    // ---- epilogue (all 128 threads reconverged): flush last chunk ----
    {
        const float* __restrict__ ring = hc[(NCHUNK - 1) & 1];
        const int s0 = (NCHUNK - 1) * CHUNK;
        #pragma unroll
        for (int r = 0; r < 2; ++r) {
            int i = tid + r * 128;
            if (i < CHUNK * OUT_) {
                int t = i & 15, o = i >> 4;
                const ulonglong2* hp =
                    reinterpret_cast<const ulonglong2*>(&ring[t * HCS]);
                const ulonglong2* wp =
                    reinterpret_cast<const ulonglong2*>(&Wdp[o * 32]);
                ull a0 = pack2(bd_sh[o], 0.0f), a1 = 0;
                #pragma unroll
                for (int g = 0; g < 16; ++g) {
                    ulonglong2 hv = hp[g];
                    ulonglong2 wv = wp[g];
                    fma2(a0, hv.x, wv.x);
                    fma2(a1, hv.y, wv.y);
                }
                float lo, hi; unpack2(add2(a0, a1), lo, hi);
                out[((size_t)b * S_ + (s0 + t)) * OUT_ + o] = lo + hi;
            }
        }
    }
}

// ---------------------------------------------------------------------------
// Entry point
// Inputs: num1[i32 B*S], num2[i32 B*S], embed[f32 10*32], Wx[f32 64*64],
//         Wh[f32 64*64], b[f32 64], Wd[f32 64*10], bd[f32 10]
// Output: float32 [B, S, 10]
// ---------------------------------------------------------------------------
extern "C" void kernel_launch(void* const* d_in, const int* in_sizes, int n_in,
                              void* d_out, int out_size) {
    const int*   num1  = (const int*)d_in[0];
    const int*   num2  = (const int*)d_in[1];
    const float* embed = (const float*)d_in[2];
    const float* Wx    = (const float*)d_in[3];
    const float* Wh    = (const float*)d_in[4];
    const float* bvec  = (const float*)d_in[5];
    const float* Wd    = (const float*)d_in[6];
    const float* bd    = (const float*)d_in[7];
    float* out = (float*)d_out;

    const int idx_blocks = (B_ * S_ + 255) / 256;
    prep_kernel<<<TAB_BLOCKS + idx_blocks, 256>>>(num1, num2, embed, Wx, bvec);

    rnn_kernel<<<B_, 128>>>(Wh, Wd, bd, out);
}